// round 10
// baseline (speedup 1.0000x reference)
#include <cuda_runtime.h>
#include <math.h>

#define SENT 147456

__device__ float g_cat2[75497472]; // 64 x 32ch x 192x192  (ch0..15 convT2 out, ch16..31 conv1 out)
__device__ float g_cat3[37748736]; // 64 x 64ch x 96x96    (ch0..31 convT3 out, ch32..63 conv2 out)
__device__ float g_a3[9437184];    // 64 x 64ch x 48x48
__device__ int   g_lab[9437184];   // 64 x 384x384
__device__ int   g_rootlist[9437184];
__device__ int   g_nroot[64];
__device__ float g_rad[1024], g_angd[1024];
__device__ int   g_ncomp[64];

// ---------- direct conv k4 s2 p1, relu. 16x16 out tile, thread = 4 px x OCS ch ----------
// Double-buffered pipeline, float4 weight loads, float2 tile loads (stride 36).
template<int IC,int ICT,int OC,int OCS,int OCT,int INW,int OUTW>
__global__ __launch_bounds__(256,2) void convk(const float* __restrict__ x, const float* __restrict__ w,
                                               const float* __restrict__ bias, float* __restrict__ y){
    constexpr int WN=(16*OC+255)/256;
    __shared__ float sw[2][16*OC];
    __shared__ float tile[2][34*36];
    __shared__ float sb[OC];
    int img=blockIdx.z, tid=threadIdx.x;
    int cg=tid>>6, ps=tid&63, px=ps&15, py0=ps>>4;
    if(tid<OC) sb[tid]=bias[tid];
    int y0=blockIdx.y*16, x0=blockIdx.x*16;
    float acc[4][OCS];
#pragma unroll
    for(int k=0;k<4;k++)
#pragma unroll
        for(int c=0;c<OCS;c++) acc[k][c]=0.f;
    const float* xb = x + (size_t)img*ICT*INW*INW;
    int iy0=y0*2-1, ix0=x0*2-1;
    int toff[5]; bool tok[5]; int tdst[5];
#pragma unroll
    for(int k=0;k<5;k++){
        int t=tid+256*k;
        int r=t/34, c=t-r*34;
        int iy=iy0+r, ix=ix0+c;
        tok[k]=(t<1156)&&iy>=0&&iy<INW&&ix>=0&&ix<INW;
        toff[k]=iy*INW+ix;
        tdst[k]=r*36+c;
    }
    int woff[WN];
#pragma unroll
    for(int j=0;j<WN;j++){
        int t=tid+256*j;
        int oc=t%OC, tap=t/OC;
        woff[j]=(t<16*OC)? oc*IC*16+tap : 0;
    }
    float tv[5], wr[WN];
    {
#pragma unroll
        for(int k=0;k<5;k++) tv[k]= tok[k]? xb[toff[k]] : 0.f;
#pragma unroll
        for(int j=0;j<WN;j++) wr[j]= w[woff[j]];
#pragma unroll
        for(int k=0;k<5;k++) if(tid+256*k<1156) tile[0][tdst[k]]=tv[k];
#pragma unroll
        for(int j=0;j<WN;j++) if(tid+256*j<16*OC) sw[0][tid+256*j]=wr[j];
    }
    __syncthreads();
    int cur=0;
    int tpx=2*px;
    for(int ic=0;ic<IC;ic++){
        if(ic+1<IC){
            const float* s=xb+(size_t)(ic+1)*INW*INW;
#pragma unroll
            for(int k=0;k<5;k++) tv[k]= tok[k]? s[toff[k]] : 0.f;
#pragma unroll
            for(int j=0;j<WN;j++) wr[j]= w[woff[j]+(ic+1)*16];
        }
#pragma unroll
        for(int kh=0;kh<4;kh++){
            float t4[4][4];
#pragma unroll
            for(int k=0;k<4;k++){
                int base=(2*(py0+4*k)+kh)*36 + tpx;
                float2 a=*(const float2*)&tile[cur][base];
                float2 b=*(const float2*)&tile[cur][base+2];
                t4[k][0]=a.x; t4[k][1]=a.y; t4[k][2]=b.x; t4[k][3]=b.y;
            }
#pragma unroll
            for(int kw=0;kw<4;kw++){
                int tap=kh*4+kw;
                float wv[OCS];
                const float4* wp=(const float4*)&sw[cur][tap*OC + cg*OCS];
#pragma unroll
                for(int q=0;q<OCS/4;q++){
                    float4 w4=wp[q];
                    wv[4*q]=w4.x; wv[4*q+1]=w4.y; wv[4*q+2]=w4.z; wv[4*q+3]=w4.w;
                }
#pragma unroll
                for(int k=0;k<4;k++){
                    float v=t4[k][kw];
#pragma unroll
                    for(int c=0;c<OCS;c++) acc[k][c]=fmaf(v,wv[c],acc[k][c]);
                }
            }
        }
        if(ic+1<IC){
            int nxt=cur^1;
#pragma unroll
            for(int k=0;k<5;k++) if(tid+256*k<1156) tile[nxt][tdst[k]]=tv[k];
#pragma unroll
            for(int j=0;j<WN;j++) if(tid+256*j<16*OC) sw[nxt][tid+256*j]=wr[j];
            __syncthreads();
            cur=nxt;
        }
    }
#pragma unroll
    for(int k=0;k<4;k++){
        int oy=y0+py0+4*k, ox=x0+px;
#pragma unroll
        for(int c=0;c<OCS;c++){
            int oc=cg*OCS+c;
            float v=acc[k][c]+sb[oc];
            y[(((size_t)img*OCT+oc)*OUTW+oy)*OUTW+ox]=v>0.f?v:0.f;
        }
    }
}

// ---------- transposed conv k4 s2 p1, relu (torch weights [in][out][kh][kw]), pipelined ----------
// No min-blocks clause: let ptxas keep all prefetch state in regs (no spills).
template<int IC,int ICT,int OC,int OCS,int OCT,int INW,int OUTW>
__global__ __launch_bounds__(256) void convtk(const float* __restrict__ x, const float* __restrict__ w,
                                              const float* __restrict__ bias, float* __restrict__ y){
    constexpr int WN=(16*OC+255)/256;
    __shared__ float sw[2][16*OC];
    __shared__ float tile[2][110];
    __shared__ float sb[OC];
    int img=blockIdx.z, tid=threadIdx.x;
    int cg=tid>>6, ps=tid&63, px=ps&15, py0=ps>>4;
    if(tid<OC) sb[tid]=bias[tid];
    int y0=blockIdx.y*16, x0=blockIdx.x*16;
    int iyLo=y0/2-1, ixLo=x0/2-1;
    int oxg=x0+px, oyb=y0+py0;
    int kw0=(oxg+1)&1, kh0=(oyb+1)&1;
    int lx =((oxg+1-kw0)>>1)-ixLo;
    int lyb=((oyb+1-kh0)>>1)-iyLo;
    float acc[4][OCS];
#pragma unroll
    for(int k=0;k<4;k++)
#pragma unroll
        for(int c=0;c<OCS;c++) acc[k][c]=0.f;
    const float* xb = x + (size_t)img*ICT*INW*INW;
    int toff=0; bool tok=false;
    if(tid<110){
        int r=tid/11, c=tid-r*11;
        int iy=iyLo+r, ix=ixLo+c;
        tok=iy>=0&&iy<INW&&ix>=0&&ix<INW;
        toff=iy*INW+ix;
    }
    int woff[WN];
#pragma unroll
    for(int j=0;j<WN;j++){
        int t=tid+256*j;
        int oc=t%OC, tap=t/OC;
        woff[j]=(t<16*OC)? oc*16+tap : 0;  // + ic*OC*16 added per ic
    }
    float tv, wr[WN];
    {
        tv = (tid<110 && tok)? xb[toff] : 0.f;
#pragma unroll
        for(int j=0;j<WN;j++) wr[j]= w[woff[j]];
        if(tid<110) tile[0][tid]=tv;
#pragma unroll
        for(int j=0;j<WN;j++) if(tid+256*j<16*OC) sw[0][tid+256*j]=wr[j];
    }
    __syncthreads();
    int cur=0;
    for(int ic=0;ic<IC;ic++){
        if(ic+1<IC){
            const float* s=xb+(size_t)(ic+1)*INW*INW;
            tv = (tid<110 && tok)? s[toff] : 0.f;
#pragma unroll
            for(int j=0;j<WN;j++) wr[j]= w[(size_t)(ic+1)*OC*16 + woff[j]];
        }
#pragma unroll
        for(int a=0;a<2;a++)
#pragma unroll
            for(int bb=0;bb<2;bb++){
                int tap=(kh0+2*a)*4 + (kw0+2*bb);
                float wv[OCS];
                const float4* wp=(const float4*)&sw[cur][tap*OC + cg*OCS];
#pragma unroll
                for(int q=0;q<OCS/4;q++){
                    float4 w4=wp[q];
                    wv[4*q]=w4.x; wv[4*q+1]=w4.y; wv[4*q+2]=w4.z; wv[4*q+3]=w4.w;
                }
#pragma unroll
                for(int k=0;k<4;k++){
                    float v=tile[cur][(lyb+2*k-a)*11 + lx-bb];
#pragma unroll
                    for(int c=0;c<OCS;c++) acc[k][c]=fmaf(v,wv[c],acc[k][c]);
                }
            }
        if(ic+1<IC){
            int nxt=cur^1;
            if(tid<110) tile[nxt][tid]=tv;
#pragma unroll
            for(int j=0;j<WN;j++) if(tid+256*j<16*OC) sw[nxt][tid+256*j]=wr[j];
            __syncthreads();
            cur=nxt;
        }
    }
#pragma unroll
    for(int k=0;k<4;k++){
        int oy=y0+py0+4*k, ox=x0+px;
#pragma unroll
        for(int c=0;c<OCS;c++){
            int oc=cg*OCS+c;
            float v=acc[k][c]+sb[oc];
            y[(((size_t)img*OCT+oc)*OUTW+oy)*OUTW+ox]=v>0.f?v:0.f;
        }
    }
}

// ---------- final transposed conv 32->1: all-ic tile in smem, one barrier ----------
__global__ __launch_bounds__(256) void convt1_k(const float* __restrict__ w, const float* __restrict__ bias){
    __shared__ float sw[512];
    __shared__ float tile[32*110];
    int img=blockIdx.z, tid=threadIdx.x;
    int ty=tid>>4, tx=tid&15;
    for(int t=tid;t<512;t+=256) sw[t]=w[t];
    float bv=bias[0];
    int y0=blockIdx.y*16, x0=blockIdx.x*16, oy=y0+ty, ox=x0+tx;
    int iyLo=y0/2-1, ixLo=x0/2-1;
    int kh0=(oy+1)&1, kw0=(ox+1)&1;
    const float* xb = g_cat2 + (size_t)img*32*36864;
    for(int t=tid;t<32*110;t+=256){
        int ic=t/110, rc=t-ic*110;
        int r=rc/11, c=rc-r*11;
        int iy=iyLo+r, ix=ixLo+c;
        tile[t]=(iy>=0&&iy<192&&ix>=0&&ix<192)? xb[(size_t)ic*36864 + iy*192+ix] : 0.f;
    }
    __syncthreads();
    int ly=((oy+1-kh0)>>1)-iyLo;
    int lxx=((ox+1-kw0)>>1)-ixLo;
    float acc=0.f;
#pragma unroll 4
    for(int ic=0;ic<32;ic++){
        const float* tp=tile+ic*110;
#pragma unroll
        for(int a=0;a<2;a++)
#pragma unroll
            for(int bb=0;bb<2;bb++)
                acc=fmaf(tp[(ly-a)*11+lxx-bb], sw[ic*16+(kh0+2*a)*4+(kw0+2*bb)], acc);
    }
    acc+=bv;
    int p=oy*384+ox;
    g_lab[(size_t)img*SENT+p] = (acc>1.0986123f)? p : SENT; // sigmoid(v)>0.75 <=> v>ln3
}

// ---------- union-find CCL (plain walk, no compression — proven on HW) ----------
__device__ __forceinline__ int uf_find(const int* L,int x){ while(L[x]!=x) x=L[x]; return x; }
__device__ void uf_merge(int* L,int a,int b){
    a=uf_find(L,a); b=uf_find(L,b);
    while(a!=b){
        if(a<b){int t=a;a=b;b=t;}
        int old=atomicMin(&L[a], b);
        if(old==a) break;
        a=old;
    }
}
__global__ void ccl_merge_k(){
    int p=blockIdx.x*256+threadIdx.x; if(p>=SENT) return;
    int* L=g_lab+(size_t)blockIdx.y*SENT;
    if(L[p]==SENT) return;
    int yy=p/384, xx=p-yy*384;
    if(xx<383 && L[p+1]!=SENT) uf_merge(L,p,p+1);
    if(yy<383){
        if(L[p+384]!=SENT) uf_merge(L,p,p+384);
        if(xx>0 && L[p+383]!=SENT) uf_merge(L,p,p+383);
        if(xx<383 && L[p+385]!=SENT) uf_merge(L,p,p+385);
    }
}
__global__ void ccl_flat_k(){
    int p=blockIdx.x*256+threadIdx.x; if(p>=SENT) return;
    int img=blockIdx.y;
    int* L=g_lab+(size_t)img*SENT;
    int v=L[p]; if(v==SENT) return;
    int r=uf_find(L,v);
    L[p]=r;
    if(p==r){ int i=atomicAdd(&g_nroot[img],1); g_rootlist[(size_t)img*SENT+i]=r; }
}

// ---------- per-image: 16 smallest roots (from root list), centroids, polar, sort ----------
__global__ __launch_bounds__(1024) void extract_k(){
    int img=blockIdx.x, tid=threadIdx.x;
    const int* L=g_lab+(size_t)img*SENT;
    const int* R=g_rootlist+(size_t)img*SENT;
    int nr=g_nroot[img];
    __shared__ int red[1024];
    __shared__ int kept[16];
    __shared__ int s_n;
    __shared__ double sx[16], sy[16];
    __shared__ int cnt[16];
    __shared__ float rr[16], aa[16];
    if(tid==0) s_n=0;
    int prev=-1;
    for(int k=0;k<16;k++){
        int m=SENT;
        for(int t=tid;t<nr;t+=1024){int v=R[t]; if(v>prev&&v<m)m=v;}
        red[tid]=m; __syncthreads();
        for(int s=512;s>0;s>>=1){ if(tid<s) red[tid]=min(red[tid],red[tid+s]); __syncthreads(); }
        int mn=red[0]; __syncthreads();
        if(mn>=SENT) break;
        if(tid==0){ kept[k]=mn; s_n=k+1; }
        prev=mn;
        __syncthreads();
    }
    __syncthreads();
    int nk=s_n;
    if(tid<16){ sx[tid]=0.0; sy[tid]=0.0; cnt[tid]=0; }
    __syncthreads();
    if(nk>0){
        for(int p=tid;p<SENT;p+=1024){
            int v=L[p];
            if(v<SENT){
                for(int j=0;j<nk;j++) if(kept[j]==v){
                    atomicAdd(&cnt[j],1);
                    atomicAdd(&sx[j],(double)(p%384));
                    atomicAdd(&sy[j],(double)(p/384));
                    break;
                }
            }
        }
    }
    __syncthreads();
    if(tid<16){
        double c = cnt[tid]>0 ? (double)cnt[tid] : 1.0;
        double cx=sx[tid]/c, cy=sy[tid]/c;
        double dx=cx-192.0, dy=cy-192.0;
        rr[tid]=(float)sqrt(dx*dx+dy*dy);
        double ang=atan2(dy,dx)*57.29577951308232;
        ang=fmod(ang,360.0); if(ang<0.0) ang+=360.0;
        aa[tid]=(float)ang;
    }
    __syncthreads();
    if(tid==0){
        int ord[16]; float key[16];
        for(int k=0;k<16;k++){ ord[k]=k; key[k]=(k<nk)? rr[k] : 3.4e38f; }
        for(int k=1;k<16;k++){
            int o=ord[k]; float kk=key[k]; int j=k-1;
            while(j>=0 && key[j]>kk){ key[j+1]=key[j]; ord[j+1]=ord[j]; j--; }
            key[j+1]=kk; ord[j+1]=o;
        }
        for(int k=0;k<16;k++){
            int o=ord[k]; bool val=(o<nk);
            g_rad[img*16+k]= val? rr[o]:0.f;
            g_angd[img*16+k]=val? aa[o]:0.f;
        }
        g_ncomp[img]=nk;
    }
}

// ---------- greedy match + MLP ----------
__global__ void match_mlp_k(const float* __restrict__ w1,const float* __restrict__ b1,
                            const float* __restrict__ w2,const float* __restrict__ b2,
                            const float* __restrict__ w3,const float* __restrict__ b3,
                            float* __restrict__ out){
    int b=threadIdx.x; if(b>=32) return;
    int n1=g_ncomp[b], n2=g_ncomp[b+32];
    bool sw = n1>n2;
    int iA = sw? b+32 : b, iB = sw? b : b+32;
    int nA = sw? n2:n1,  nB = sw? n1:n2;
    float rA[16],aA[16],rB[16],aB[16]; bool used[16];
    for(int k=0;k<16;k++){
        rA[k]=g_rad[iA*16+k]; aA[k]=g_angd[iA*16+k];
        rB[k]=g_rad[iB*16+k]; aB[k]=g_angd[iB*16+k];
        used[k]=false;
    }
    float feat[32];
    for(int i=0;i<16;i++){
        bool vi = i<nA;
        float best=3.4e38f; int j=0;
        for(int q=0;q<16;q++){
            float d=(used[q]||q>=nB)? 3.4e38f : fabsf(rB[q]-rA[i]);
            if(d<best){best=d;j=q;}
        }
        float dr=rA[i]-rB[j];
        float da=fabsf(sinf((aA[i]-aB[j])*0.017453292519943295f));
        feat[2*i]  = vi? dr:0.f;
        feat[2*i+1]= vi? da:0.f;
        if(vi) used[j]=true;
    }
    float h1[32];
    for(int k=0;k<32;k++){ float s=b1[k]; for(int j=0;j<32;j++) s=fmaf(feat[j],w1[k*32+j],s); h1[k]=s>0.f?s:0.f; }
    float h2[8];
    for(int k=0;k<8;k++){ float s=b2[k]; for(int j=0;j<32;j++) s=fmaf(h1[j],w2[k*32+j],s); h2[k]=s>0.f?s:0.f; }
    float s=b3[0]; for(int k=0;k<8;k++) s=fmaf(h2[k],w3[k],s);
    out[b]=s;
}

extern "C" void kernel_launch(void* const* d_in, const int* in_sizes, int n_in,
                              void* d_out, int out_size){
    const float* x1 =(const float*)d_in[0];
    const float* x2 =(const float*)d_in[1];
    const float* e1w=(const float*)d_in[2],  *e1b=(const float*)d_in[3];
    const float* e2w=(const float*)d_in[4],  *e2b=(const float*)d_in[5];
    const float* e3w=(const float*)d_in[6],  *e3b=(const float*)d_in[7];
    const float* d3w=(const float*)d_in[8],  *d3b=(const float*)d_in[9];
    const float* d2w=(const float*)d_in[10], *d2b=(const float*)d_in[11];
    const float* d1w=(const float*)d_in[12], *d1b=(const float*)d_in[13];
    const float* w1 =(const float*)d_in[14], *b1=(const float*)d_in[15];
    const float* w2 =(const float*)d_in[16], *b2=(const float*)d_in[17];
    const float* w3 =(const float*)d_in[18], *b3=(const float*)d_in[19];
    float* out=(float*)d_out;

    float *cat2,*cat3,*a3; int* nroot;
    cudaGetSymbolAddress((void**)&cat2, g_cat2);
    cudaGetSymbolAddress((void**)&cat3, g_cat3);
    cudaGetSymbolAddress((void**)&a3,   g_a3);
    cudaGetSymbolAddress((void**)&nroot,g_nroot);

    cudaMemsetAsync(nroot, 0, 64*sizeof(int));

    // conv1 (1->16, 384->192) into cat2 ch16..31
    convk<1,1,16,4,32,384,192><<<dim3(12,12,32),256>>>(x1, e1w, e1b, cat2 + (size_t)16*36864);
    convk<1,1,16,4,32,384,192><<<dim3(12,12,32),256>>>(x2, e1w, e1b, cat2 + (size_t)32*32*36864 + (size_t)16*36864);
    // conv2 (16->32, 192->96): input = cat2 ch16..31, per-image stride 32 ch
    convk<16,32,32,8,64,192,96><<<dim3(6,6,64),256>>>(cat2 + (size_t)16*36864, e2w, e2b, cat3 + (size_t)32*9216);
    // conv3 (32->64, 96->48) split into two OC halves: input = cat3 ch32..63
    convk<32,64,32,8,64,96,48><<<dim3(3,3,64),256>>>(cat3 + (size_t)32*9216, e3w, e3b, a3);
    convk<32,64,32,8,64,96,48><<<dim3(3,3,64),256>>>(cat3 + (size_t)32*9216, e3w + 32*32*16, e3b + 32, a3 + (size_t)32*2304);
    // convT3 (64->32, 48->96) into cat3 ch0..31
    convtk<64,64,32,8,64,48,96><<<dim3(6,6,64),256>>>(a3, d3w, d3b, cat3);
    // convT2 (64->16, 96->192) into cat2 ch0..15
    convtk<64,64,16,4,32,96,192><<<dim3(12,12,64),256>>>(cat3, d2w, d2b, cat2);
    // convT1 (32->1, 192->384) -> labels
    convt1_k<<<dim3(24,24,64),256>>>(d1w, d1b);
    // CCL
    ccl_merge_k<<<dim3(576,64),256>>>();
    ccl_flat_k<<<dim3(576,64),256>>>();
    // features
    extract_k<<<64,1024>>>();
    // match + MLP
    match_mlp_k<<<1,32>>>(w1,b1,w2,b2,w3,b3,out);
}

// round 11
// speedup vs baseline: 1.5295x; 1.5295x over previous
#include <cuda_runtime.h>
#include <math.h>

#define SENT 147456

__device__ float g_cat2[75497472]; // 64 x 32ch x 192x192  (ch0..15 convT2 out, ch16..31 conv1 out)
__device__ float g_cat3[37748736]; // 64 x 64ch x 96x96    (ch0..31 convT3 out, ch32..63 conv2 out)
__device__ float g_a3[9437184];    // 64 x 64ch x 48x48
__device__ int   g_lab[9437184];   // 64 x 384x384
__device__ int   g_rootlist[9437184];
__device__ int   g_nroot[64];
__device__ float g_rad[1024], g_angd[1024];
__device__ int   g_ncomp[64];

// ---------- direct conv k4 s2 p1, relu. 16x16 out tile, thread = 4 px x OCS ch ----------
// Double-buffered pipeline, float4 weight loads, float2 tile loads (stride 36).
// HALVES: OC-split factor folded into blockIdx.z (z = img*HALVES + half) for wave packing.
template<int IC,int ICT,int OC,int OCS,int OCT,int HALVES,int INW,int OUTW>
__global__ __launch_bounds__(256,2) void convk(const float* __restrict__ x, const float* __restrict__ w,
                                               const float* __restrict__ bias, float* __restrict__ y){
    constexpr int WN=(16*OC+255)/256;
    __shared__ float sw[2][16*OC];
    __shared__ float tile[2][34*36];
    __shared__ float sb[OC];
    int z=blockIdx.z, tid=threadIdx.x;
    int img = z/HALVES;
    int half= z - img*HALVES;
    w    += (size_t)half*OC*IC*16;
    bias += half*OC;
    int cg=tid>>6, ps=tid&63, px=ps&15, py0=ps>>4;
    if(tid<OC) sb[tid]=bias[tid];
    int y0=blockIdx.y*16, x0=blockIdx.x*16;
    float acc[4][OCS];
#pragma unroll
    for(int k=0;k<4;k++)
#pragma unroll
        for(int c=0;c<OCS;c++) acc[k][c]=0.f;
    const float* xb = x + (size_t)img*ICT*INW*INW;
    int iy0=y0*2-1, ix0=x0*2-1;
    int toff[5]; bool tok[5]; int tdst[5];
#pragma unroll
    for(int k=0;k<5;k++){
        int t=tid+256*k;
        int r=t/34, c=t-r*34;
        int iy=iy0+r, ix=ix0+c;
        tok[k]=(t<1156)&&iy>=0&&iy<INW&&ix>=0&&ix<INW;
        toff[k]=iy*INW+ix;
        tdst[k]=r*36+c;
    }
    int woff[WN];
#pragma unroll
    for(int j=0;j<WN;j++){
        int t=tid+256*j;
        int oc=t%OC, tap=t/OC;
        woff[j]=(t<16*OC)? oc*IC*16+tap : 0;
    }
    float tv[5], wr[WN];
    {
#pragma unroll
        for(int k=0;k<5;k++) tv[k]= tok[k]? xb[toff[k]] : 0.f;
#pragma unroll
        for(int j=0;j<WN;j++) wr[j]= w[woff[j]];
#pragma unroll
        for(int k=0;k<5;k++) if(tid+256*k<1156) tile[0][tdst[k]]=tv[k];
#pragma unroll
        for(int j=0;j<WN;j++) if(tid+256*j<16*OC) sw[0][tid+256*j]=wr[j];
    }
    __syncthreads();
    int cur=0;
    int tpx=2*px;
    for(int ic=0;ic<IC;ic++){
        if(ic+1<IC){
            const float* s=xb+(size_t)(ic+1)*INW*INW;
#pragma unroll
            for(int k=0;k<5;k++) tv[k]= tok[k]? s[toff[k]] : 0.f;
#pragma unroll
            for(int j=0;j<WN;j++) wr[j]= w[woff[j]+(ic+1)*16];
        }
#pragma unroll
        for(int kh=0;kh<4;kh++){
            float t4[4][4];
#pragma unroll
            for(int k=0;k<4;k++){
                int base=(2*(py0+4*k)+kh)*36 + tpx;
                float2 a=*(const float2*)&tile[cur][base];
                float2 b=*(const float2*)&tile[cur][base+2];
                t4[k][0]=a.x; t4[k][1]=a.y; t4[k][2]=b.x; t4[k][3]=b.y;
            }
#pragma unroll
            for(int kw=0;kw<4;kw++){
                int tap=kh*4+kw;
                float wv[OCS];
                const float4* wp=(const float4*)&sw[cur][tap*OC + cg*OCS];
#pragma unroll
                for(int q=0;q<OCS/4;q++){
                    float4 w4=wp[q];
                    wv[4*q]=w4.x; wv[4*q+1]=w4.y; wv[4*q+2]=w4.z; wv[4*q+3]=w4.w;
                }
#pragma unroll
                for(int k=0;k<4;k++){
                    float v=t4[k][kw];
#pragma unroll
                    for(int c=0;c<OCS;c++) acc[k][c]=fmaf(v,wv[c],acc[k][c]);
                }
            }
        }
        if(ic+1<IC){
            int nxt=cur^1;
#pragma unroll
            for(int k=0;k<5;k++) if(tid+256*k<1156) tile[nxt][tdst[k]]=tv[k];
#pragma unroll
            for(int j=0;j<WN;j++) if(tid+256*j<16*OC) sw[nxt][tid+256*j]=wr[j];
            __syncthreads();
            cur=nxt;
        }
    }
#pragma unroll
    for(int k=0;k<4;k++){
        int oy=y0+py0+4*k, ox=x0+px;
#pragma unroll
        for(int c=0;c<OCS;c++){
            int oc=cg*OCS+c;
            float v=acc[k][c]+sb[oc];
            y[(((size_t)img*OCT+half*OC+oc)*OUTW+oy)*OUTW+ox]=v>0.f?v:0.f;
        }
    }
}

// ---------- transposed conv k4 s2 p1, relu (torch weights [in][out][kh][kw]), pipelined ----------
// No min-blocks clause: let ptxas keep all prefetch state in regs (no spills).
template<int IC,int ICT,int OC,int OCS,int OCT,int INW,int OUTW>
__global__ __launch_bounds__(256) void convtk(const float* __restrict__ x, const float* __restrict__ w,
                                              const float* __restrict__ bias, float* __restrict__ y){
    constexpr int WN=(16*OC+255)/256;
    __shared__ float sw[2][16*OC];
    __shared__ float tile[2][110];
    __shared__ float sb[OC];
    int img=blockIdx.z, tid=threadIdx.x;
    int cg=tid>>6, ps=tid&63, px=ps&15, py0=ps>>4;
    if(tid<OC) sb[tid]=bias[tid];
    int y0=blockIdx.y*16, x0=blockIdx.x*16;
    int iyLo=y0/2-1, ixLo=x0/2-1;
    int oxg=x0+px, oyb=y0+py0;
    int kw0=(oxg+1)&1, kh0=(oyb+1)&1;
    int lx =((oxg+1-kw0)>>1)-ixLo;
    int lyb=((oyb+1-kh0)>>1)-iyLo;
    float acc[4][OCS];
#pragma unroll
    for(int k=0;k<4;k++)
#pragma unroll
        for(int c=0;c<OCS;c++) acc[k][c]=0.f;
    const float* xb = x + (size_t)img*ICT*INW*INW;
    int toff=0; bool tok=false;
    if(tid<110){
        int r=tid/11, c=tid-r*11;
        int iy=iyLo+r, ix=ixLo+c;
        tok=iy>=0&&iy<INW&&ix>=0&&ix<INW;
        toff=iy*INW+ix;
    }
    int woff[WN];
#pragma unroll
    for(int j=0;j<WN;j++){
        int t=tid+256*j;
        int oc=t%OC, tap=t/OC;
        woff[j]=(t<16*OC)? oc*16+tap : 0;  // + ic*OC*16 added per ic
    }
    float tv, wr[WN];
    {
        tv = (tid<110 && tok)? xb[toff] : 0.f;
#pragma unroll
        for(int j=0;j<WN;j++) wr[j]= w[woff[j]];
        if(tid<110) tile[0][tid]=tv;
#pragma unroll
        for(int j=0;j<WN;j++) if(tid+256*j<16*OC) sw[0][tid+256*j]=wr[j];
    }
    __syncthreads();
    int cur=0;
    for(int ic=0;ic<IC;ic++){
        if(ic+1<IC){
            const float* s=xb+(size_t)(ic+1)*INW*INW;
            tv = (tid<110 && tok)? s[toff] : 0.f;
#pragma unroll
            for(int j=0;j<WN;j++) wr[j]= w[(size_t)(ic+1)*OC*16 + woff[j]];
        }
#pragma unroll
        for(int a=0;a<2;a++)
#pragma unroll
            for(int bb=0;bb<2;bb++){
                int tap=(kh0+2*a)*4 + (kw0+2*bb);
                float wv[OCS];
                const float4* wp=(const float4*)&sw[cur][tap*OC + cg*OCS];
#pragma unroll
                for(int q=0;q<OCS/4;q++){
                    float4 w4=wp[q];
                    wv[4*q]=w4.x; wv[4*q+1]=w4.y; wv[4*q+2]=w4.z; wv[4*q+3]=w4.w;
                }
#pragma unroll
                for(int k=0;k<4;k++){
                    float v=tile[cur][(lyb+2*k-a)*11 + lx-bb];
#pragma unroll
                    for(int c=0;c<OCS;c++) acc[k][c]=fmaf(v,wv[c],acc[k][c]);
                }
            }
        if(ic+1<IC){
            int nxt=cur^1;
            if(tid<110) tile[nxt][tid]=tv;
#pragma unroll
            for(int j=0;j<WN;j++) if(tid+256*j<16*OC) sw[nxt][tid+256*j]=wr[j];
            __syncthreads();
            cur=nxt;
        }
    }
#pragma unroll
    for(int k=0;k<4;k++){
        int oy=y0+py0+4*k, ox=x0+px;
#pragma unroll
        for(int c=0;c<OCS;c++){
            int oc=cg*OCS+c;
            float v=acc[k][c]+sb[oc];
            y[(((size_t)img*OCT+oc)*OUTW+oy)*OUTW+ox]=v>0.f?v:0.f;
        }
    }
}

// ---------- final transposed conv 32->1: all-ic tile in smem, one barrier ----------
__global__ __launch_bounds__(256) void convt1_k(const float* __restrict__ w, const float* __restrict__ bias){
    __shared__ float sw[512];
    __shared__ float tile[32*110];
    int img=blockIdx.z, tid=threadIdx.x;
    int ty=tid>>4, tx=tid&15;
    for(int t=tid;t<512;t+=256) sw[t]=w[t];
    float bv=bias[0];
    int y0=blockIdx.y*16, x0=blockIdx.x*16, oy=y0+ty, ox=x0+tx;
    int iyLo=y0/2-1, ixLo=x0/2-1;
    int kh0=(oy+1)&1, kw0=(ox+1)&1;
    const float* xb = g_cat2 + (size_t)img*32*36864;
    for(int t=tid;t<32*110;t+=256){
        int ic=t/110, rc=t-ic*110;
        int r=rc/11, c=rc-r*11;
        int iy=iyLo+r, ix=ixLo+c;
        tile[t]=(iy>=0&&iy<192&&ix>=0&&ix<192)? xb[(size_t)ic*36864 + iy*192+ix] : 0.f;
    }
    __syncthreads();
    int ly=((oy+1-kh0)>>1)-iyLo;
    int lxx=((ox+1-kw0)>>1)-ixLo;
    float acc=0.f;
#pragma unroll 4
    for(int ic=0;ic<32;ic++){
        const float* tp=tile+ic*110;
#pragma unroll
        for(int a=0;a<2;a++)
#pragma unroll
            for(int bb=0;bb<2;bb++)
                acc=fmaf(tp[(ly-a)*11+lxx-bb], sw[ic*16+(kh0+2*a)*4+(kw0+2*bb)], acc);
    }
    acc+=bv;
    int p=oy*384+ox;
    g_lab[(size_t)img*SENT+p] = (acc>1.0986123f)? p : SENT; // sigmoid(v)>0.75 <=> v>ln3
}

// ---------- union-find CCL (plain walk, no compression — proven on HW) ----------
__device__ __forceinline__ int uf_find(const int* L,int x){ while(L[x]!=x) x=L[x]; return x; }
__device__ void uf_merge(int* L,int a,int b){
    a=uf_find(L,a); b=uf_find(L,b);
    while(a!=b){
        if(a<b){int t=a;a=b;b=t;}
        int old=atomicMin(&L[a], b);
        if(old==a) break;
        a=old;
    }
}
__global__ void ccl_merge_k(){
    int p=blockIdx.x*256+threadIdx.x; if(p>=SENT) return;
    int* L=g_lab+(size_t)blockIdx.y*SENT;
    if(L[p]==SENT) return;
    int yy=p/384, xx=p-yy*384;
    if(xx<383 && L[p+1]!=SENT) uf_merge(L,p,p+1);
    if(yy<383){
        if(L[p+384]!=SENT) uf_merge(L,p,p+384);
        if(xx>0 && L[p+383]!=SENT) uf_merge(L,p,p+383);
        if(xx<383 && L[p+385]!=SENT) uf_merge(L,p,p+385);
    }
}
__global__ void ccl_flat_k(){
    int p=blockIdx.x*256+threadIdx.x; if(p>=SENT) return;
    int img=blockIdx.y;
    int* L=g_lab+(size_t)img*SENT;
    int v=L[p]; if(v==SENT) return;
    int r=uf_find(L,v);
    L[p]=r;
    if(p==r){ int i=atomicAdd(&g_nroot[img],1); g_rootlist[(size_t)img*SENT+i]=r; }
}

// ---------- per-image: 16 smallest roots (from root list), centroids, polar, sort ----------
__global__ __launch_bounds__(1024) void extract_k(){
    int img=blockIdx.x, tid=threadIdx.x;
    const int* L=g_lab+(size_t)img*SENT;
    const int* R=g_rootlist+(size_t)img*SENT;
    int nr=g_nroot[img];
    __shared__ int red[1024];
    __shared__ int kept[16];
    __shared__ int s_n;
    __shared__ double sx[16], sy[16];
    __shared__ int cnt[16];
    __shared__ float rr[16], aa[16];
    if(tid==0) s_n=0;
    int prev=-1;
    for(int k=0;k<16;k++){
        int m=SENT;
        for(int t=tid;t<nr;t+=1024){int v=R[t]; if(v>prev&&v<m)m=v;}
        red[tid]=m; __syncthreads();
        for(int s=512;s>0;s>>=1){ if(tid<s) red[tid]=min(red[tid],red[tid+s]); __syncthreads(); }
        int mn=red[0]; __syncthreads();
        if(mn>=SENT) break;
        if(tid==0){ kept[k]=mn; s_n=k+1; }
        prev=mn;
        __syncthreads();
    }
    __syncthreads();
    int nk=s_n;
    if(tid<16){ sx[tid]=0.0; sy[tid]=0.0; cnt[tid]=0; }
    __syncthreads();
    if(nk>0){
        for(int p=tid;p<SENT;p+=1024){
            int v=L[p];
            if(v<SENT){
                for(int j=0;j<nk;j++) if(kept[j]==v){
                    atomicAdd(&cnt[j],1);
                    atomicAdd(&sx[j],(double)(p%384));
                    atomicAdd(&sy[j],(double)(p/384));
                    break;
                }
            }
        }
    }
    __syncthreads();
    if(tid<16){
        double c = cnt[tid]>0 ? (double)cnt[tid] : 1.0;
        double cx=sx[tid]/c, cy=sy[tid]/c;
        double dx=cx-192.0, dy=cy-192.0;
        rr[tid]=(float)sqrt(dx*dx+dy*dy);
        double ang=atan2(dy,dx)*57.29577951308232;
        ang=fmod(ang,360.0); if(ang<0.0) ang+=360.0;
        aa[tid]=(float)ang;
    }
    __syncthreads();
    if(tid==0){
        int ord[16]; float key[16];
        for(int k=0;k<16;k++){ ord[k]=k; key[k]=(k<nk)? rr[k] : 3.4e38f; }
        for(int k=1;k<16;k++){
            int o=ord[k]; float kk=key[k]; int j=k-1;
            while(j>=0 && key[j]>kk){ key[j+1]=key[j]; ord[j+1]=ord[j]; j--; }
            key[j+1]=kk; ord[j+1]=o;
        }
        for(int k=0;k<16;k++){
            int o=ord[k]; bool val=(o<nk);
            g_rad[img*16+k]= val? rr[o]:0.f;
            g_angd[img*16+k]=val? aa[o]:0.f;
        }
        g_ncomp[img]=nk;
    }
}

// ---------- greedy match + MLP ----------
__global__ void match_mlp_k(const float* __restrict__ w1,const float* __restrict__ b1,
                            const float* __restrict__ w2,const float* __restrict__ b2,
                            const float* __restrict__ w3,const float* __restrict__ b3,
                            float* __restrict__ out){
    int b=threadIdx.x; if(b>=32) return;
    int n1=g_ncomp[b], n2=g_ncomp[b+32];
    bool sw = n1>n2;
    int iA = sw? b+32 : b, iB = sw? b : b+32;
    int nA = sw? n2:n1,  nB = sw? n1:n2;
    float rA[16],aA[16],rB[16],aB[16]; bool used[16];
    for(int k=0;k<16;k++){
        rA[k]=g_rad[iA*16+k]; aA[k]=g_angd[iA*16+k];
        rB[k]=g_rad[iB*16+k]; aB[k]=g_angd[iB*16+k];
        used[k]=false;
    }
    float feat[32];
    for(int i=0;i<16;i++){
        bool vi = i<nA;
        float best=3.4e38f; int j=0;
        for(int q=0;q<16;q++){
            float d=(used[q]||q>=nB)? 3.4e38f : fabsf(rB[q]-rA[i]);
            if(d<best){best=d;j=q;}
        }
        float dr=rA[i]-rB[j];
        float da=fabsf(sinf((aA[i]-aB[j])*0.017453292519943295f));
        feat[2*i]  = vi? dr:0.f;
        feat[2*i+1]= vi? da:0.f;
        if(vi) used[j]=true;
    }
    float h1[32];
    for(int k=0;k<32;k++){ float s=b1[k]; for(int j=0;j<32;j++) s=fmaf(feat[j],w1[k*32+j],s); h1[k]=s>0.f?s:0.f; }
    float h2[8];
    for(int k=0;k<8;k++){ float s=b2[k]; for(int j=0;j<32;j++) s=fmaf(h1[j],w2[k*32+j],s); h2[k]=s>0.f?s:0.f; }
    float s=b3[0]; for(int k=0;k<8;k++) s=fmaf(h2[k],w3[k],s);
    out[b]=s;
}

extern "C" void kernel_launch(void* const* d_in, const int* in_sizes, int n_in,
                              void* d_out, int out_size){
    const float* x1 =(const float*)d_in[0];
    const float* x2 =(const float*)d_in[1];
    const float* e1w=(const float*)d_in[2],  *e1b=(const float*)d_in[3];
    const float* e2w=(const float*)d_in[4],  *e2b=(const float*)d_in[5];
    const float* e3w=(const float*)d_in[6],  *e3b=(const float*)d_in[7];
    const float* d3w=(const float*)d_in[8],  *d3b=(const float*)d_in[9];
    const float* d2w=(const float*)d_in[10], *d2b=(const float*)d_in[11];
    const float* d1w=(const float*)d_in[12], *d1b=(const float*)d_in[13];
    const float* w1 =(const float*)d_in[14], *b1=(const float*)d_in[15];
    const float* w2 =(const float*)d_in[16], *b2=(const float*)d_in[17];
    const float* w3 =(const float*)d_in[18], *b3=(const float*)d_in[19];
    float* out=(float*)d_out;

    float *cat2,*cat3,*a3; int* nroot;
    cudaGetSymbolAddress((void**)&cat2, g_cat2);
    cudaGetSymbolAddress((void**)&cat3, g_cat3);
    cudaGetSymbolAddress((void**)&a3,   g_a3);
    cudaGetSymbolAddress((void**)&nroot,g_nroot);

    cudaMemsetAsync(nroot, 0, 64*sizeof(int));

    // conv1 (1->16, 384->192) into cat2 ch16..31
    convk<1,1,16,4,32,1,384,192><<<dim3(12,12,32),256>>>(x1, e1w, e1b, cat2 + (size_t)16*36864);
    convk<1,1,16,4,32,1,384,192><<<dim3(12,12,32),256>>>(x2, e1w, e1b, cat2 + (size_t)32*32*36864 + (size_t)16*36864);
    // conv2 (16->32, 192->96): input = cat2 ch16..31, per-image stride 32 ch
    convk<16,32,32,8,64,1,192,96><<<dim3(6,6,64),256>>>(cat2 + (size_t)16*36864, e2w, e2b, cat3 + (size_t)32*9216);
    // conv3 (32->64, 96->48): ONE launch, z = img*2 + oc-half (wave packing)
    convk<32,64,32,8,64,2,96,48><<<dim3(3,3,128),256>>>(cat3 + (size_t)32*9216, e3w, e3b, a3);
    // convT3 (64->32, 48->96) into cat3 ch0..31
    convtk<64,64,32,8,64,48,96><<<dim3(6,6,64),256>>>(a3, d3w, d3b, cat3);
    // convT2 (64->16, 96->192) into cat2 ch0..15
    convtk<64,64,16,4,32,96,192><<<dim3(12,12,64),256>>>(cat3, d2w, d2b, cat2);
    // convT1 (32->1, 192->384) -> labels
    convt1_k<<<dim3(24,24,64),256>>>(d1w, d1b);
    // CCL
    ccl_merge_k<<<dim3(576,64),256>>>();
    ccl_flat_k<<<dim3(576,64),256>>>();
    // features
    extract_k<<<64,1024>>>();
    // match + MLP
    match_mlp_k<<<1,32>>>(w1,b1,w2,b2,w3,b3,out);
}